// round 1
// baseline (speedup 1.0000x reference)
#include <cuda_runtime.h>
#include <math.h>

#define BB_  2
#define CC   128
#define HH   128
#define WW   128
#define SRR  8
#define MOFF 17
#define IP   289
#define MIDC 144
#define OPC  49
#define HW   (HH*WW)

// ---------------- scratch (static device globals; no runtime allocation) ----------------
__device__ float g_rn [BB_*HW];                      // 1/||f1||_c per pixel
__device__ float g_mv [(size_t)BB_*IP*HW];           // match volume (post leaky)
__device__ float g_att[(size_t)BB_*IP*HW];           // att_vol = mv * att
__device__ float g_mid[(size_t)BB_*MIDC*HW];         // conv1 output

// ---------------- kernel 1: per-pixel inverse L2 norm of f1 over channels ----------------
__global__ void k_rnorm(const float* __restrict__ f1) {
    int idx = blockIdx.x * 256 + threadIdx.x;
    if (idx >= BB_*HW) return;
    int b = idx / HW, p = idx % HW;
    const float* base = f1 + (size_t)b*CC*HW + p;
    float s = 0.f;
#pragma unroll 8
    for (int c = 0; c < CC; c++) { float v = base[(size_t)c*HW]; s = fmaf(v, v, s); }
    g_rn[idx] = 1.f / fmaxf(sqrtf(s), 1e-12f);
}

// ---------------- kernel 2: cost volume (17x17 local correlation) + leaky ----------------
// block: (w-tile of 64, h, b). 272 threads: tid -> pixel-group g = tid&15 (4 px each),
// dy = tid>>4 (0..16). Each thread keeps acc[17 dx][4 px] in registers.
__global__ __launch_bounds__(272) void k_costvol(const float* __restrict__ f1,
                                                 const float* __restrict__ f2) {
    __shared__ float s_x1[64];
    __shared__ float s_f2[MOFF * 80];

    const int x0  = blockIdx.x * 64;
    const int h   = blockIdx.y;
    const int b   = blockIdx.z;
    const int tid = threadIdx.x;
    const int g   = tid & 15;
    const int dy  = tid >> 4;

    float acc[MOFF][4];
#pragma unroll
    for (int d = 0; d < MOFF; d++)
#pragma unroll
        for (int j = 0; j < 4; j++) acc[d][j] = 0.f;

    const float* f1b = f1 + (size_t)b*CC*HW;
    const float* f2b = f2 + (size_t)b*CC*HW;
    const float* rnb = g_rn + (size_t)b*HW + h*WW + x0;

    for (int c = 0; c < CC; c++) {
        // stage normalized f1 row segment
        for (int i = tid; i < 64; i += 272)
            s_x1[i] = f1b[(size_t)c*HW + h*WW + x0 + i] * rnb[i];
        // stage f2 window: 17 rows (h-8..h+8) x 80 cols (x0-8..x0+71), zero-padded
        for (int i = tid; i < MOFF*80; i += 272) {
            int r  = i / 80, col = i % 80;
            int gy = h + r - SRR;
            int gx = x0 + col - SRR;
            float v = 0.f;
            if (gy >= 0 && gy < HH && gx >= 0 && gx < WW)
                v = f2b[(size_t)c*HW + gy*WW + gx];
            s_f2[i] = v;
        }
        __syncthreads();

        float4 x1v = *(const float4*)&s_x1[g*4];
        float f2v[20];
#pragma unroll
        for (int q = 0; q < 5; q++) {
            float4 t = *(const float4*)&s_f2[dy*80 + g*4 + q*4];
            f2v[q*4+0] = t.x; f2v[q*4+1] = t.y; f2v[q*4+2] = t.z; f2v[q*4+3] = t.w;
        }
#pragma unroll
        for (int dx = 0; dx < MOFF; dx++) {
            acc[dx][0] = fmaf(x1v.x, f2v[dx+0], acc[dx][0]);
            acc[dx][1] = fmaf(x1v.y, f2v[dx+1], acc[dx][1]);
            acc[dx][2] = fmaf(x1v.z, f2v[dx+2], acc[dx][2]);
            acc[dx][3] = fmaf(x1v.w, f2v[dx+3], acc[dx][3]);
        }
        __syncthreads();
    }

#pragma unroll
    for (int dx = 0; dx < MOFF; dx++) {
        float4 o;
        float* op = (float*)&o;
#pragma unroll
        for (int j = 0; j < 4; j++) {
            float v = acc[dx][j] * 0.0078125f;   // mean over 128 channels
            op[j] = v > 0.f ? v : 0.1f * v;      // leaky_relu(0.1)
        }
        int ch = dy*MOFF + dx;
        *(float4*)&g_mv[(((size_t)b*IP + ch)*HH + h)*WW + x0 + g*4] = o;
    }
}

// ---------------- kernel 3: depthwise 7x7 att conv + bias, then att_vol = mv*att --------
// block: (w-tile 32, h-tile 8, b*289+ch). 256 threads, one output each.
__global__ void k_att(const float* __restrict__ att_w, const float* __restrict__ att_b) {
    __shared__ float s_in[14*38];
    __shared__ float s_w[49];

    const int bz = blockIdx.z;
    const int b  = bz / IP;
    const int ch = bz % IP;
    const int x0 = blockIdx.x * 32;
    const int y0 = blockIdx.y * 8;
    const int tid = threadIdx.x;

    const float* mvp = g_mv + ((size_t)b*IP + ch)*HW;
    for (int i = tid; i < 14*38; i += 256) {
        int r = i / 38, cl = i % 38;
        int gy = y0 + r - 3, gx = x0 + cl - 3;
        s_in[i] = (gy >= 0 && gy < HH && gx >= 0 && gx < WW) ? mvp[gy*WW + gx] : 0.f;
    }
    if (tid < 49) s_w[tid] = att_w[ch*49 + tid];
    __syncthreads();

    const int tx = tid & 31, ty = tid >> 5;
    float s = att_b[ch];
#pragma unroll
    for (int ky = 0; ky < 7; ky++)
#pragma unroll
        for (int kx = 0; kx < 7; kx++)
            s = fmaf(s_w[ky*7+kx], s_in[(ty+ky)*38 + tx + kx], s);

    float center = s_in[(ty+3)*38 + tx + 3];
    g_att[((size_t)b*IP + ch)*HW + (y0+ty)*WW + x0 + tx] = center * s;
}

// ---------------- kernels 4/5: 3x3 conv + BN(eval) + exact GELU ----------------
// block: (w-tile 16, h-tile 16, b*nCoTiles + coTile). 256 threads:
// thread = (co-group of 4) x (2x2 pixel micro-tile).
template<int CIN, int COUT, bool IS_CONV2>
__global__ __launch_bounds__(256) void k_conv3x3(const float* __restrict__ wgt,
                                                 const float* __restrict__ bg,
                                                 const float* __restrict__ bb,
                                                 const float* __restrict__ bm,
                                                 const float* __restrict__ bv,
                                                 float* __restrict__ dout) {
    __shared__ float s_in[18*18];
    __shared__ float s_w[16*9];

    constexpr int nCo = (COUT + 15) / 16;
    const int b   = blockIdx.z / nCo;
    const int co0 = (blockIdx.z % nCo) * 16;
    const int x0  = blockIdx.x * 16;
    const int y0  = blockIdx.y * 16;
    const int tid = threadIdx.x;
    const int cg  = tid >> 6;        // 0..3 (4 co each)
    const int pt  = tid & 63;
    const int ptx = pt & 7;          // 0..7
    const int pty = pt >> 3;         // 0..7

    const float* inb = (IS_CONV2 ? g_mid : g_att) + (size_t)b*CIN*HW;
    float*       out = IS_CONV2 ? dout : g_mid;

    float acc[2][2][4];
#pragma unroll
    for (int iy = 0; iy < 2; iy++)
#pragma unroll
        for (int ix = 0; ix < 2; ix++)
#pragma unroll
            for (int k = 0; k < 4; k++) acc[iy][ix][k] = 0.f;

    for (int ci = 0; ci < CIN; ci++) {
        for (int i = tid; i < 18*18; i += 256) {
            int r = i / 18, cl = i % 18;
            int gy = y0 + r - 1, gx = x0 + cl - 1;
            s_in[i] = (gy >= 0 && gy < HH && gx >= 0 && gx < WW)
                          ? inb[(size_t)ci*HW + gy*WW + gx] : 0.f;
        }
        if (tid < 16*9) {
            int co = co0 + tid / 9;
            s_w[tid] = (co < COUT) ? wgt[((size_t)co*CIN + ci)*9 + tid%9] : 0.f;
        }
        __syncthreads();

        float v[4][4];
#pragma unroll
        for (int r = 0; r < 4; r++)
#pragma unroll
            for (int cI = 0; cI < 4; cI++)
                v[r][cI] = s_in[(2*pty + r)*18 + 2*ptx + cI];

#pragma unroll
        for (int k = 0; k < 4; k++) {
#pragma unroll
            for (int ky = 0; ky < 3; ky++)
#pragma unroll
                for (int kx = 0; kx < 3; kx++) {
                    float wv = s_w[(cg*4 + k)*9 + ky*3 + kx];
                    acc[0][0][k] = fmaf(wv, v[ky+0][kx+0], acc[0][0][k]);
                    acc[0][1][k] = fmaf(wv, v[ky+0][kx+1], acc[0][1][k]);
                    acc[1][0][k] = fmaf(wv, v[ky+1][kx+0], acc[1][0][k]);
                    acc[1][1][k] = fmaf(wv, v[ky+1][kx+1], acc[1][1][k]);
                }
        }
        __syncthreads();
    }

#pragma unroll
    for (int k = 0; k < 4; k++) {
        int co = co0 + cg*4 + k;
        if (co < COUT) {
            float scale = bg[co] * rsqrtf(bv[co] + 1e-5f);
            float mean  = bm[co];
            float beta  = bb[co];
#pragma unroll
            for (int iy = 0; iy < 2; iy++)
#pragma unroll
                for (int ix = 0; ix < 2; ix++) {
                    float z = (acc[iy][ix][k] - mean) * scale + beta;
                    float gel = 0.5f * z * (1.f + erff(z * 0.70710678118654752440f));
                    out[(((size_t)b*COUT + co)*HH + y0 + 2*pty + iy)*WW + x0 + 2*ptx + ix] = gel;
                }
        }
    }
}

// ---------------- launch ----------------
extern "C" void kernel_launch(void* const* d_in, const int* in_sizes, int n_in,
                              void* d_out, int out_size) {
    const float* f1    = (const float*)d_in[0];
    const float* f2    = (const float*)d_in[1];
    const float* att_w = (const float*)d_in[2];
    const float* att_b = (const float*)d_in[3];
    const float* c1_w  = (const float*)d_in[4];
    const float* bn1_g = (const float*)d_in[5];
    const float* bn1_b = (const float*)d_in[6];
    const float* bn1_m = (const float*)d_in[7];
    const float* bn1_v = (const float*)d_in[8];
    const float* c2_w  = (const float*)d_in[9];
    const float* bn2_g = (const float*)d_in[10];
    const float* bn2_b = (const float*)d_in[11];
    const float* bn2_m = (const float*)d_in[12];
    const float* bn2_v = (const float*)d_in[13];

    k_rnorm<<<(BB_*HW + 255)/256, 256>>>(f1);
    k_costvol<<<dim3(WW/64, HH, BB_), 272>>>(f1, f2);
    k_att<<<dim3(WW/32, HH/8, BB_*IP), 256>>>(att_w, att_b);
    k_conv3x3<IP,  MIDC, false><<<dim3(8, 8, BB_*9), 256>>>(c1_w, bn1_g, bn1_b, bn1_m, bn1_v, nullptr);
    k_conv3x3<MIDC, OPC, true ><<<dim3(8, 8, BB_*4), 256>>>(c2_w, bn2_g, bn2_b, bn2_m, bn2_v, (float*)d_out);
}

// round 3
// speedup vs baseline: 1.6900x; 1.6900x over previous
#include <cuda_runtime.h>
#include <cuda_bf16.h>
#include <math.h>
#include <stdint.h>

#define BB_  2
#define CC   128
#define HH   128
#define WW   128
#define SRR  8
#define MOFF 17
#define IP   289
#define MIDC 144
#define OPC  49
#define HW   (HH*WW)

#define CPAD   320            // 289 padded to 5*64
#define NCHUNK 5
#define NTAP   9
#define KCHUNKS (NTAP*NCHUNK) // 45

// ---------------- scratch (static device globals; no runtime allocation) ----------------
__device__ float g_rn [BB_*HW];
__device__ float g_mv [(size_t)BB_*IP*HW];
__device__ float g_att[(size_t)BB_*IP*HW];
__device__ float g_mid[(size_t)BB_*MIDC*HW];
__device__ __nv_bfloat16 g_atth[(size_t)BB_*HW*CPAD];   // NHWC hi split
__device__ __nv_bfloat16 g_attl[(size_t)BB_*HW*CPAD];   // NHWC lo split
__device__ __nv_bfloat16 g_w1h [NTAP*NCHUNK*MIDC*64];   // [t][c][co][ci]
__device__ __nv_bfloat16 g_w1l [NTAP*NCHUNK*MIDC*64];

// ---------------- helpers ----------------
__device__ __forceinline__ uint32_t smem_u32(const void* p) {
    uint32_t a;
    asm("{ .reg .u64 t; cvta.to.shared.u64 t, %1; cvt.u32.u64 %0, t; }" : "=r"(a) : "l"(p));
    return a;
}
#define SWZ(o) ((o) ^ (((o) >> 3) & 0x70))

__device__ __forceinline__ void cpa16(uint32_t saddr, const void* gaddr, uint32_t sz) {
    asm volatile("cp.async.cg.shared.global [%0], [%1], 16, %2;"
                 :: "r"(saddr), "l"(gaddr), "r"(sz));
}
#define CPA_COMMIT() asm volatile("cp.async.commit_group;" ::: "memory")
#define CPA_WAIT0()  asm volatile("cp.async.wait_group 0;" ::: "memory")
#define CPA_WAIT1()  asm volatile("cp.async.wait_group 1;" ::: "memory")

__device__ __forceinline__ void ldsm4(uint32_t addr, uint32_t* r) {
    asm volatile("ldmatrix.sync.aligned.m8n8.x4.shared.b16 {%0,%1,%2,%3}, [%4];"
                 : "=r"(r[0]), "=r"(r[1]), "=r"(r[2]), "=r"(r[3]) : "r"(addr));
}
__device__ __forceinline__ void ldsm2(uint32_t addr, uint32_t* r) {
    asm volatile("ldmatrix.sync.aligned.m8n8.x2.shared.b16 {%0,%1}, [%2];"
                 : "=r"(r[0]), "=r"(r[1]) : "r"(addr));
}
__device__ __forceinline__ void mma16816(float* d, const uint32_t* a, const uint32_t* b) {
    asm volatile("mma.sync.aligned.m16n8k16.row.col.f32.bf16.bf16.f32 "
                 "{%0,%1,%2,%3}, {%4,%5,%6,%7}, {%8,%9}, {%0,%1,%2,%3};"
                 : "+f"(d[0]), "+f"(d[1]), "+f"(d[2]), "+f"(d[3])
                 : "r"(a[0]), "r"(a[1]), "r"(a[2]), "r"(a[3]), "r"(b[0]), "r"(b[1]));
}

// ---------------- kernel 1: per-pixel inverse L2 norm of f1 over channels ----------------
__global__ void k_rnorm(const float* __restrict__ f1) {
    int idx = blockIdx.x * 256 + threadIdx.x;
    if (idx >= BB_*HW) return;
    int b = idx / HW, p = idx % HW;
    const float* base = f1 + (size_t)b*CC*HW + p;
    float s = 0.f;
#pragma unroll 8
    for (int c = 0; c < CC; c++) { float v = base[(size_t)c*HW]; s = fmaf(v, v, s); }
    g_rn[idx] = 1.f / fmaxf(sqrtf(s), 1e-12f);
}

// ---------------- kernel 2: cost volume (17x17 local correlation) + leaky ----------------
__global__ __launch_bounds__(272) void k_costvol(const float* __restrict__ f1,
                                                 const float* __restrict__ f2) {
    __shared__ float s_x1[64];
    __shared__ float s_f2[MOFF * 80];

    const int x0  = blockIdx.x * 64;
    const int h   = blockIdx.y;
    const int b   = blockIdx.z;
    const int tid = threadIdx.x;
    const int g   = tid & 15;
    const int dy  = tid >> 4;

    float acc[MOFF][4];
#pragma unroll
    for (int d = 0; d < MOFF; d++)
#pragma unroll
        for (int j = 0; j < 4; j++) acc[d][j] = 0.f;

    const float* f1b = f1 + (size_t)b*CC*HW;
    const float* f2b = f2 + (size_t)b*CC*HW;
    const float* rnb = g_rn + (size_t)b*HW + h*WW + x0;

    for (int c = 0; c < CC; c++) {
        for (int i = tid; i < 64; i += 272)
            s_x1[i] = f1b[(size_t)c*HW + h*WW + x0 + i] * rnb[i];
        for (int i = tid; i < MOFF*80; i += 272) {
            int r  = i / 80, col = i % 80;
            int gy = h + r - SRR;
            int gx = x0 + col - SRR;
            float v = 0.f;
            if (gy >= 0 && gy < HH && gx >= 0 && gx < WW)
                v = f2b[(size_t)c*HW + gy*WW + gx];
            s_f2[i] = v;
        }
        __syncthreads();

        float4 x1v = *(const float4*)&s_x1[g*4];
        float f2v[20];
#pragma unroll
        for (int q = 0; q < 5; q++) {
            float4 t = *(const float4*)&s_f2[dy*80 + g*4 + q*4];
            f2v[q*4+0] = t.x; f2v[q*4+1] = t.y; f2v[q*4+2] = t.z; f2v[q*4+3] = t.w;
        }
#pragma unroll
        for (int dx = 0; dx < MOFF; dx++) {
            acc[dx][0] = fmaf(x1v.x, f2v[dx+0], acc[dx][0]);
            acc[dx][1] = fmaf(x1v.y, f2v[dx+1], acc[dx][1]);
            acc[dx][2] = fmaf(x1v.z, f2v[dx+2], acc[dx][2]);
            acc[dx][3] = fmaf(x1v.w, f2v[dx+3], acc[dx][3]);
        }
        __syncthreads();
    }

#pragma unroll
    for (int dx = 0; dx < MOFF; dx++) {
        float4 o;
        float* op = (float*)&o;
#pragma unroll
        for (int j = 0; j < 4; j++) {
            float v = acc[dx][j] * 0.0078125f;
            op[j] = v > 0.f ? v : 0.1f * v;
        }
        int ch = dy*MOFF + dx;
        *(float4*)&g_mv[(((size_t)b*IP + ch)*HH + h)*WW + x0 + g*4] = o;
    }
}

// ---------------- kernel 3: depthwise 7x7 att conv + bias, att_vol = mv*att ----------
__global__ void k_att(const float* __restrict__ att_w, const float* __restrict__ att_b) {
    __shared__ float s_in[14*38];
    __shared__ float s_w[49];

    const int bz = blockIdx.z;
    const int b  = bz / IP;
    const int ch = bz % IP;
    const int x0 = blockIdx.x * 32;
    const int y0 = blockIdx.y * 8;
    const int tid = threadIdx.x;

    const float* mvp = g_mv + ((size_t)b*IP + ch)*HW;
    for (int i = tid; i < 14*38; i += 256) {
        int r = i / 38, cl = i % 38;
        int gy = y0 + r - 3, gx = x0 + cl - 3;
        s_in[i] = (gy >= 0 && gy < HH && gx >= 0 && gx < WW) ? mvp[gy*WW + gx] : 0.f;
    }
    if (tid < 49) s_w[tid] = att_w[ch*49 + tid];
    __syncthreads();

    const int tx = tid & 31, ty = tid >> 5;
    float s = att_b[ch];
#pragma unroll
    for (int ky = 0; ky < 7; ky++)
#pragma unroll
        for (int kx = 0; kx < 7; kx++)
            s = fmaf(s_w[ky*7+kx], s_in[(ty+ky)*38 + tx + kx], s);

    float center = s_in[(ty+3)*38 + tx + 3];
    g_att[((size_t)b*IP + ch)*HW + (y0+ty)*WW + x0 + tx] = center * s;
}

// ---------------- kernel 4: transpose NCHW fp32 -> NHWC bf16 hi/lo (C padded 320) ----
__global__ __launch_bounds__(256) void k_nhwc() {
    __shared__ float s[32][33];
    const int tid = threadIdx.x;
    const int tx = tid & 31, ty = tid >> 5;
    const int px0 = blockIdx.x * 32;
    const int ch0 = blockIdx.y * 32;
    const int b   = blockIdx.z;

#pragma unroll
    for (int j = 0; j < 4; j++) {
        int ch = ch0 + j*8 + ty;
        s[j*8 + ty][tx] = (ch < IP) ? g_att[((size_t)b*IP + ch)*HW + px0 + tx] : 0.f;
    }
    __syncthreads();
#pragma unroll
    for (int j = 0; j < 4; j++) {
        int px = px0 + j*8 + ty;
        float v = s[tx][j*8 + ty];
        __nv_bfloat16 hi = __float2bfloat16(v);
        __nv_bfloat16 lo = __float2bfloat16(v - __bfloat162float(hi));
        size_t o = (size_t)(b*HW + px)*CPAD + ch0 + tx;
        g_atth[o] = hi;
        g_attl[o] = lo;
    }
}

// ---------------- kernel 5: conv1 weights -> [tap][chunk][co][ci=64] bf16 hi/lo ----
__global__ void k_prepw(const float* __restrict__ w) {
    int i = blockIdx.x * 256 + threadIdx.x;
    if (i >= NTAP*NCHUNK*MIDC*64) return;
    int ci_in = i & 63;
    int co    = (i >> 6) % MIDC;
    int tc    = (i >> 6) / MIDC;
    int c     = tc % NCHUNK;
    int t     = tc / NCHUNK;
    int ci    = c*64 + ci_in;
    float v = (ci < IP) ? w[((size_t)co*IP + ci)*9 + t] : 0.f;
    __nv_bfloat16 hi = __float2bfloat16(v);
    __nv_bfloat16 lo = __float2bfloat16(v - __bfloat162float(hi));
    g_w1h[i] = hi;
    g_w1l[i] = lo;
}

// ---------------- kernel 6: conv1 implicit GEMM on mma.sync bf16 (3-term split) --------
// CTA = one image row y: M=128 px, N=144 co, K = 45 chunks of 64.
#define STG_BYTES 69632       // A_hi 16K | A_lo 16K | B_hi 18K | B_lo 18K
#define OFF_AH 0
#define OFF_AL 16384
#define OFF_BH 32768
#define OFF_BL 51200
#define SM_BN   (2*STG_BYTES)         // 139264
#define SMEM_G  (SM_BN + 3*MIDC*4 + 64)

__device__ __forceinline__ void stage_async(uint32_t sb_stage, int tid, int kc, int b, int y) {
    const int t = kc / NCHUNK, c = kc - t*NCHUNK;
    const int ky = t / 3, kx = t - ky*3;
    const int ysrc = y + ky - 1;
    const bool yok = ((unsigned)ysrc < (unsigned)HH);
    const int gyc = yok ? ysrc : 0;

    // A: 2 splits x 128 px-rows x 8 x 16B
#pragma unroll
    for (int j = 0; j < 8; j++) {
        int i = tid + j*256;
        int split = i >> 10, idx = i & 1023, px = idx >> 3, q = idx & 7;
        int xsrc = px + kx - 1;
        bool ok = yok && ((unsigned)xsrc < (unsigned)WW);
        int gxc = ok ? xsrc : 0;
        const __nv_bfloat16* src = split ? g_attl : g_atth;
        const void* gp = src + ((size_t)((b*HH + gyc)*WW + gxc))*CPAD + c*64 + q*8;
        uint32_t off = (uint32_t)(px*128 + q*16);
        cpa16(sb_stage + split*16384 + SWZ(off), gp, ok ? 16u : 0u);
    }
    // B: 2 splits x 144 co-rows x 8 x 16B
    const __nv_bfloat16* wh = g_w1h + (size_t)(t*NCHUNK + c)*MIDC*64;
    const __nv_bfloat16* wl = g_w1l + (size_t)(t*NCHUNK + c)*MIDC*64;
#pragma unroll
    for (int j = 0; j < 9; j++) {
        int i = tid + j*256;
        int split = (i >= 1152);
        int idx = i - split*1152, row = idx >> 3, q = idx & 7;
        const __nv_bfloat16* src = split ? wl : wh;
        uint32_t off = (uint32_t)(row*128 + q*16);
        cpa16(sb_stage + OFF_BH + split*18432 + SWZ(off), src + row*64 + q*8, 16u);
    }
}

__global__ __launch_bounds__(256, 1) void k_gemm1(const float* __restrict__ bg,
                                                  const float* __restrict__ bb,
                                                  const float* __restrict__ bm,
                                                  const float* __restrict__ bv) {
    extern __shared__ char smem[];
    const int tid  = threadIdx.x;
    const int wid  = tid >> 5, lane = tid & 31;
    const int y    = blockIdx.x & (HH - 1);
    const int b    = blockIdx.x >> 7;
    const uint32_t sb = smem_u32(smem);

    float* sScale = (float*)(smem + SM_BN);
    float* sMean  = sScale + MIDC;
    float* sBeta  = sMean + MIDC;
    if (tid < MIDC) {
        sScale[tid] = bg[tid] * rsqrtf(bv[tid] + 1e-5f);
        sMean[tid]  = bm[tid];
        sBeta[tid]  = bb[tid];
    }

    const int wm = wid & 3, wn = wid >> 2;

    // per-lane ldmatrix address components
    const int gA = lane >> 3;
    const int arow_off = (lane & 7) + ((gA & 1) << 3);
    const uint32_t acol_g = (uint32_t)((gA >> 1) << 4);
    const uint32_t swzx   = (uint32_t)((lane & 7) << 4);
    const int brow_off = ((gA >> 1) << 3) + (lane & 7);
    const uint32_t bcol_g = (uint32_t)((gA & 1) << 4);
    const int l2 = lane & 15;
    const int b2row_off = 64 + (l2 & 7);
    const uint32_t b2col_g = (uint32_t)((l2 >> 3) << 4);
    const uint32_t swz2   = (uint32_t)((l2 & 7) << 4);

    float acc[2][9][4];
#pragma unroll
    for (int mf = 0; mf < 2; mf++)
#pragma unroll
        for (int nf = 0; nf < 9; nf++)
#pragma unroll
            for (int k = 0; k < 4; k++) acc[mf][nf][k] = 0.f;

    stage_async(sb, tid, 0, b, y);
    CPA_COMMIT();

    for (int kc = 0; kc < KCHUNKS; kc++) {
        if (kc + 1 < KCHUNKS) {
            stage_async(sb + ((kc + 1) & 1) * STG_BYTES, tid, kc + 1, b, y);
            CPA_COMMIT();
            CPA_WAIT1();
        } else {
            CPA_WAIT0();
        }
        __syncthreads();

        const uint32_t base = sb + (kc & 1) * STG_BYTES;
        const uint32_t aH = base + OFF_AH + (uint32_t)(wm * 32) * 128;
        const uint32_t aL = base + OFF_AL + (uint32_t)(wm * 32) * 128;
        const uint32_t bH = base + OFF_BH + (uint32_t)(wn * 72) * 128;
        const uint32_t bL = base + OFF_BL + (uint32_t)(wn * 72) * 128;

#pragma unroll
        for (int ks = 0; ks < 4; ks++) {
            uint32_t ah[2][4], al[2][4], bh[9][2], bl[9][2];
            const uint32_t colA = ((uint32_t)(ks * 32) + acol_g) ^ swzx;
#pragma unroll
            for (int mf = 0; mf < 2; mf++) {
                uint32_t ra = (uint32_t)(mf * 16 + arow_off) * 128;
                ldsm4(aH + ra + colA, ah[mf]);
                ldsm4(aL + ra + colA, al[mf]);
            }
            const uint32_t colB = ((uint32_t)(ks * 32) + bcol_g) ^ swzx;
#pragma unroll
            for (int nf = 0; nf < 8; nf += 2) {
                uint32_t rb = (uint32_t)(nf * 8 + brow_off) * 128;
                uint32_t tmp[4];
                ldsm4(bH + rb + colB, tmp);
                bh[nf][0] = tmp[0]; bh[nf][1] = tmp[1];
                bh[nf+1][0] = tmp[2]; bh[nf+1][1] = tmp[3];
                ldsm4(bL + rb + colB, tmp);
                bl[nf][0] = tmp[0]; bl[nf][1] = tmp[1];
                bl[nf+1][0] = tmp[2]; bl[nf+1][1] = tmp[3];
            }
            {
                const uint32_t colB2 = ((uint32_t)(ks * 32) + b2col_g) ^ swz2;
                uint32_t rb2 = (uint32_t)b2row_off * 128;
                ldsm2(bH + rb2 + colB2, bh[8]);
                ldsm2(bL + rb2 + colB2, bl[8]);
            }
#pragma unroll
            for (int nf = 0; nf < 9; nf++)
#pragma unroll
                for (int mf = 0; mf < 2; mf++) {
                    mma16816(acc[mf][nf], ah[mf], bh[nf]);
                    mma16816(acc[mf][nf], ah[mf], bl[nf]);
                    mma16816(acc[mf][nf], al[mf], bh[nf]);
                }
        }
        __syncthreads();
    }

    // epilogue: BN + exact GELU, scatter to NCHW g_mid
    float* outb = g_mid + (size_t)b * MIDC * HW + (size_t)y * WW;
#pragma unroll
    for (int mf = 0; mf < 2; mf++)
#pragma unroll
        for (int nf = 0; nf < 9; nf++) {
            int co0 = wn * 72 + nf * 8 + (lane & 3) * 2;
            int x0  = wm * 32 + mf * 16 + (lane >> 2);
#pragma unroll
            for (int hr = 0; hr < 2; hr++) {
                int x = x0 + hr * 8;
#pragma unroll
                for (int dc = 0; dc < 2; dc++) {
                    int co = co0 + dc;
                    float v = acc[mf][nf][hr * 2 + dc];
                    float z = (v - sMean[co]) * sScale[co] + sBeta[co];
                    float gel = 0.5f * z * (1.f + erff(z * 0.70710678118654752440f));
                    outb[(size_t)co * HW + x] = gel;
                }
            }
        }
}

// ---------------- kernel 7: conv2 3x3 + BN + GELU (scalar) ----------------
template<int CIN, int COUT>
__global__ __launch_bounds__(256) void k_conv3x3b(const float* __restrict__ wgt,
                                                  const float* __restrict__ bg,
                                                  const float* __restrict__ bb,
                                                  const float* __restrict__ bm,
                                                  const float* __restrict__ bv,
                                                  float* __restrict__ dout) {
    __shared__ float s_in[18*18];
    __shared__ float s_w[16*9];

    constexpr int nCo = (COUT + 15) / 16;
    const int b   = blockIdx.z / nCo;
    const int co0 = (blockIdx.z % nCo) * 16;
    const int x0  = blockIdx.x * 16;
    const int y0  = blockIdx.y * 16;
    const int tid = threadIdx.x;
    const int cg  = tid >> 6;
    const int pt  = tid & 63;
    const int ptx = pt & 7;
    const int pty = pt >> 3;

    const float* inb = g_mid + (size_t)b*CIN*HW;

    float acc[2][2][4];
#pragma unroll
    for (int iy = 0; iy < 2; iy++)
#pragma unroll
        for (int ix = 0; ix < 2; ix++)
#pragma unroll
            for (int k = 0; k < 4; k++) acc[iy][ix][k] = 0.f;

    for (int ci = 0; ci < CIN; ci++) {
        for (int i = tid; i < 18*18; i += 256) {
            int r = i / 18, cl = i % 18;
            int gy = y0 + r - 1, gx = x0 + cl - 1;
            s_in[i] = (gy >= 0 && gy < HH && gx >= 0 && gx < WW)
                          ? inb[(size_t)ci*HW + gy*WW + gx] : 0.f;
        }
        if (tid < 16*9) {
            int co = co0 + tid / 9;
            s_w[tid] = (co < COUT) ? wgt[((size_t)co*CIN + ci)*9 + tid%9] : 0.f;
        }
        __syncthreads();

        float v[4][4];
#pragma unroll
        for (int r = 0; r < 4; r++)
#pragma unroll
            for (int cI = 0; cI < 4; cI++)
                v[r][cI] = s_in[(2*pty + r)*18 + 2*ptx + cI];

#pragma unroll
        for (int k = 0; k < 4; k++) {
#pragma unroll
            for (int ky = 0; ky < 3; ky++)
#pragma unroll
                for (int kx = 0; kx < 3; kx++) {
                    float wv = s_w[(cg*4 + k)*9 + ky*3 + kx];
                    acc[0][0][k] = fmaf(wv, v[ky+0][kx+0], acc[0][0][k]);
                    acc[0][1][k] = fmaf(wv, v[ky+0][kx+1], acc[0][1][k]);
                    acc[1][0][k] = fmaf(wv, v[ky+1][kx+0], acc[1][0][k]);
                    acc[1][1][k] = fmaf(wv, v[ky+1][kx+1], acc[1][1][k]);
                }
        }
        __syncthreads();
    }

#pragma unroll
    for (int k = 0; k < 4; k++) {
        int co = co0 + cg*4 + k;
        if (co < COUT) {
            float scale = bg[co] * rsqrtf(bv[co] + 1e-5f);
            float mean  = bm[co];
            float beta  = bb[co];
#pragma unroll
            for (int iy = 0; iy < 2; iy++)
#pragma unroll
                for (int ix = 0; ix < 2; ix++) {
                    float z = (acc[iy][ix][k] - mean) * scale + beta;
                    float gel = 0.5f * z * (1.f + erff(z * 0.70710678118654752440f));
                    dout[(((size_t)b*COUT + co)*HH + y0 + 2*pty + iy)*WW + x0 + 2*ptx + ix] = gel;
                }
        }
    }
}

// ---------------- launch ----------------
extern "C" void kernel_launch(void* const* d_in, const int* in_sizes, int n_in,
                              void* d_out, int out_size) {
    const float* f1    = (const float*)d_in[0];
    const float* f2    = (const float*)d_in[1];
    const float* att_w = (const float*)d_in[2];
    const float* att_b = (const float*)d_in[3];
    const float* c1_w  = (const float*)d_in[4];
    const float* bn1_g = (const float*)d_in[5];
    const float* bn1_b = (const float*)d_in[6];
    const float* bn1_m = (const float*)d_in[7];
    const float* bn1_v = (const float*)d_in[8];
    const float* c2_w  = (const float*)d_in[9];
    const float* bn2_g = (const float*)d_in[10];
    const float* bn2_b = (const float*)d_in[11];
    const float* bn2_m = (const float*)d_in[12];
    const float* bn2_v = (const float*)d_in[13];

    cudaFuncSetAttribute(k_gemm1, cudaFuncAttributeMaxDynamicSharedMemorySize, SMEM_G);

    k_rnorm<<<(BB_*HW + 255)/256, 256>>>(f1);
    k_costvol<<<dim3(WW/64, HH, BB_), 272>>>(f1, f2);
    k_att<<<dim3(WW/32, HH/8, BB_*IP), 256>>>(att_w, att_b);
    k_nhwc<<<dim3(HW/32, (IP+31)/32, BB_), 256>>>();
    k_prepw<<<(NTAP*NCHUNK*MIDC*64 + 255)/256, 256>>>(c1_w);
    k_gemm1<<<BB_*HH, 256, SMEM_G>>>(bn1_g, bn1_b, bn1_m, bn1_v);
    k_conv3x3b<MIDC, OPC><<<dim3(8, 8, BB_*4), 256>>>(c2_w, bn2_g, bn2_b, bn2_m, bn2_v, (float*)d_out);
}

// round 4
// speedup vs baseline: 2.7001x; 1.5977x over previous
#include <cuda_runtime.h>
#include <cuda_bf16.h>
#include <math.h>
#include <stdint.h>

#define BB_  2
#define CC   128
#define HH   128
#define WW   128
#define SRR  8
#define MOFF 17
#define IP   289
#define MIDC 144
#define OPC  49
#define HW   (HH*WW)

#define CPAD   320            // 289 padded to 5*64
#define NCHUNK 5
#define NTAP   9
#define KCHUNKS (NTAP*NCHUNK) // 45

#define CPAD2  192            // 144 padded to 3*64
#define OPAD   56             // 49 padded to 7*8
#define KC2    (NTAP*3)       // 27

// ---------------- scratch (static device globals; no runtime allocation) ----------------
__device__ float g_rn [BB_*HW];
__device__ float g_mv [(size_t)BB_*IP*HW];
__device__ float g_att[(size_t)BB_*IP*HW];
__device__ __nv_bfloat16 g_atth[(size_t)BB_*HW*CPAD];   // NHWC hi split (conv1 input)
__device__ __nv_bfloat16 g_attl[(size_t)BB_*HW*CPAD];   // NHWC lo split
__device__ __nv_bfloat16 g_midh[(size_t)BB_*HW*CPAD2];  // NHWC hi split (conv2 input)
__device__ __nv_bfloat16 g_midl[(size_t)BB_*HW*CPAD2];  // NHWC lo split
__device__ __nv_bfloat16 g_w1h [NTAP*NCHUNK*MIDC*64];   // [t][c][co][ci]
__device__ __nv_bfloat16 g_w1l [NTAP*NCHUNK*MIDC*64];
__device__ __nv_bfloat16 g_w2h [NTAP*3*OPAD*64];        // [t][c][co][ci]
__device__ __nv_bfloat16 g_w2l [NTAP*3*OPAD*64];

// ---------------- helpers ----------------
__device__ __forceinline__ uint32_t smem_u32(const void* p) {
    uint32_t a;
    asm("{ .reg .u64 t; cvta.to.shared.u64 t, %1; cvt.u32.u64 %0, t; }" : "=r"(a) : "l"(p));
    return a;
}
#define SWZ(o) ((o) ^ (((o) >> 3) & 0x70))

__device__ __forceinline__ void cpa16(uint32_t saddr, const void* gaddr, uint32_t sz) {
    asm volatile("cp.async.cg.shared.global [%0], [%1], 16, %2;"
                 :: "r"(saddr), "l"(gaddr), "r"(sz));
}
#define CPA_COMMIT() asm volatile("cp.async.commit_group;" ::: "memory")
#define CPA_WAIT0()  asm volatile("cp.async.wait_group 0;" ::: "memory")
#define CPA_WAIT1()  asm volatile("cp.async.wait_group 1;" ::: "memory")

__device__ __forceinline__ void ldsm4(uint32_t addr, uint32_t* r) {
    asm volatile("ldmatrix.sync.aligned.m8n8.x4.shared.b16 {%0,%1,%2,%3}, [%4];"
                 : "=r"(r[0]), "=r"(r[1]), "=r"(r[2]), "=r"(r[3]) : "r"(addr));
}
__device__ __forceinline__ void ldsm2(uint32_t addr, uint32_t* r) {
    asm volatile("ldmatrix.sync.aligned.m8n8.x2.shared.b16 {%0,%1}, [%2];"
                 : "=r"(r[0]), "=r"(r[1]) : "r"(addr));
}
__device__ __forceinline__ void mma16816(float* d, const uint32_t* a, const uint32_t* b) {
    asm volatile("mma.sync.aligned.m16n8k16.row.col.f32.bf16.bf16.f32 "
                 "{%0,%1,%2,%3}, {%4,%5,%6,%7}, {%8,%9}, {%0,%1,%2,%3};"
                 : "+f"(d[0]), "+f"(d[1]), "+f"(d[2]), "+f"(d[3])
                 : "r"(a[0]), "r"(a[1]), "r"(a[2]), "r"(a[3]), "r"(b[0]), "r"(b[1]));
}
__device__ __forceinline__ float gelu_exact(float z) {
    return 0.5f * z * (1.f + erff(z * 0.70710678118654752440f));
}

// ---------------- kernel 1: per-pixel inverse L2 norm of f1 over channels ----------------
__global__ void k_rnorm(const float* __restrict__ f1) {
    int idx = blockIdx.x * 256 + threadIdx.x;
    if (idx >= BB_*HW) return;
    int b = idx / HW, p = idx % HW;
    const float* base = f1 + (size_t)b*CC*HW + p;
    float s = 0.f;
#pragma unroll 8
    for (int c = 0; c < CC; c++) { float v = base[(size_t)c*HW]; s = fmaf(v, v, s); }
    g_rn[idx] = 1.f / fmaxf(sqrtf(s), 1e-12f);
}

// ---------------- kernel 2: cost volume, cp.async triple-buffered ----------------
// block: 64-px row tile. 272 threads: g=tid&15 (4 px), dy=tid>>4.
// f2 window 17x80 staged as 340 float4 slots; validity is float4-uniform.
__global__ __launch_bounds__(272) void k_costvol(const float* __restrict__ f1,
                                                 const float* __restrict__ f2) {
    __shared__ float s_x1[3][64];
    __shared__ float s_f2[3][MOFF*80];

    const int x0  = blockIdx.x * 64;
    const int h   = blockIdx.y;
    const int b   = blockIdx.z;
    const int tid = threadIdx.x;
    const int g   = tid & 15;
    const int dy  = tid >> 4;

    const float* f1b = f1 + (size_t)b*CC*HW;
    const float* f2b = f2 + (size_t)b*CC*HW;

    // staging descriptors (computed once)
    int   goff[2];  uint32_t smoff[2];  uint32_t csz[2];  int nslot = 1;
    {
        int slots[2] = { tid, tid + 272 };
        if (slots[1] < 340) nslot = 2;
#pragma unroll
        for (int k = 0; k < 2; k++) {
            int sl = slots[k] < 340 ? slots[k] : 0;
            int r = sl / 20, col4 = (sl % 20) * 4;
            int gy = h + r - SRR, gx0 = x0 + col4 - SRR;
            bool ok = (gy >= 0 && gy < HH && gx0 >= 0 && gx0 <= WW - 4);
            goff[k]  = ok ? (gy*WW + gx0) : 0;
            csz[k]   = ok ? 16u : 0u;
            smoff[k] = (uint32_t)((r*80 + col4) * 4);
        }
    }
    const uint32_t sb_f2 = smem_u32(&s_f2[0][0]);
    const uint32_t sb_x1 = smem_u32(&s_x1[0][0]);

    float rnv = 0.f;  const float* x1p = nullptr;
    if (tid < 64) {
        rnv = g_rn[(size_t)b*HW + h*WW + x0 + tid];
        x1p = f1b + h*WW + x0 + tid;
    }

    float acc[MOFF][4];
#pragma unroll
    for (int d = 0; d < MOFF; d++)
#pragma unroll
        for (int j = 0; j < 4; j++) acc[d][j] = 0.f;

    // prologue
    {
        const float* src = f2b;
        cpa16(sb_f2 + smoff[0], src + goff[0], csz[0]);
        if (nslot == 2) cpa16(sb_f2 + smoff[1], src + goff[1], csz[1]);
        CPA_COMMIT();
    }
    float x1cur = (tid < 64) ? x1p[0] : 0.f;
    float x1nxt = 0.f;

    for (int c = 0; c < CC; c++) {
        const int buf = c - (c/3)*3;
        if (c + 1 < CC) {
            if (tid < 64) x1nxt = x1p[(size_t)(c+1)*HW];
            const int nbuf = (c+1) - ((c+1)/3)*3;
            const float* src = f2b + (size_t)(c+1)*HW;
            uint32_t base = sb_f2 + (uint32_t)nbuf * (MOFF*80*4);
            cpa16(base + smoff[0], src + goff[0], csz[0]);
            if (nslot == 2) cpa16(base + smoff[1], src + goff[1], csz[1]);
            CPA_COMMIT();
            CPA_WAIT1();
        } else {
            CPA_WAIT0();
        }
        if (tid < 64) s_x1[buf][tid] = x1cur * rnv;
        __syncthreads();

        float4 x1v = *(const float4*)&s_x1[buf][g*4];
        float f2v[20];
        const float* row = &s_f2[buf][dy*80 + g*4];
#pragma unroll
        for (int q = 0; q < 5; q++) {
            float4 t = *(const float4*)&row[q*4];
            f2v[q*4+0] = t.x; f2v[q*4+1] = t.y; f2v[q*4+2] = t.z; f2v[q*4+3] = t.w;
        }
#pragma unroll
        for (int dx = 0; dx < MOFF; dx++) {
            acc[dx][0] = fmaf(x1v.x, f2v[dx+0], acc[dx][0]);
            acc[dx][1] = fmaf(x1v.y, f2v[dx+1], acc[dx][1]);
            acc[dx][2] = fmaf(x1v.z, f2v[dx+2], acc[dx][2]);
            acc[dx][3] = fmaf(x1v.w, f2v[dx+3], acc[dx][3]);
        }
        x1cur = x1nxt;
        __syncthreads();
    }

#pragma unroll
    for (int dx = 0; dx < MOFF; dx++) {
        float4 o;
        float* op = (float*)&o;
#pragma unroll
        for (int j = 0; j < 4; j++) {
            float v = acc[dx][j] * 0.0078125f;
            op[j] = v > 0.f ? v : 0.1f * v;
        }
        int ch = dy*MOFF + dx;
        *(float4*)&g_mv[(((size_t)b*IP + ch)*HH + h)*WW + x0 + g*4] = o;
    }
}

// ---------------- kernel 3: depthwise 7x7 att conv + bias, att_vol = mv*att ----------
__global__ void k_att(const float* __restrict__ att_w, const float* __restrict__ att_b) {
    __shared__ float s_in[14*38];
    __shared__ float s_w[49];

    const int bz = blockIdx.z;
    const int b  = bz / IP;
    const int ch = bz % IP;
    const int x0 = blockIdx.x * 32;
    const int y0 = blockIdx.y * 8;
    const int tid = threadIdx.x;

    const float* mvp = g_mv + ((size_t)b*IP + ch)*HW;
    for (int i = tid; i < 14*38; i += 256) {
        int r = i / 38, cl = i % 38;
        int gy = y0 + r - 3, gx = x0 + cl - 3;
        s_in[i] = (gy >= 0 && gy < HH && gx >= 0 && gx < WW) ? mvp[gy*WW + gx] : 0.f;
    }
    if (tid < 49) s_w[tid] = att_w[ch*49 + tid];
    __syncthreads();

    const int tx = tid & 31, ty = tid >> 5;
    float s = att_b[ch];
#pragma unroll
    for (int ky = 0; ky < 7; ky++)
#pragma unroll
        for (int kx = 0; kx < 7; kx++)
            s = fmaf(s_w[ky*7+kx], s_in[(ty+ky)*38 + tx + kx], s);

    float center = s_in[(ty+3)*38 + tx + 3];
    g_att[((size_t)b*IP + ch)*HW + (y0+ty)*WW + x0 + tx] = center * s;
}

// ---------------- kernel 4: transpose NCHW fp32 -> NHWC bf16 hi/lo (C padded 320) ----
__global__ __launch_bounds__(256) void k_nhwc() {
    __shared__ float s[32][33];
    const int tid = threadIdx.x;
    const int tx = tid & 31, ty = tid >> 5;
    const int px0 = blockIdx.x * 32;
    const int ch0 = blockIdx.y * 32;
    const int b   = blockIdx.z;

#pragma unroll
    for (int j = 0; j < 4; j++) {
        int ch = ch0 + j*8 + ty;
        s[j*8 + ty][tx] = (ch < IP) ? g_att[((size_t)b*IP + ch)*HW + px0 + tx] : 0.f;
    }
    __syncthreads();
#pragma unroll
    for (int j = 0; j < 4; j++) {
        int px = px0 + j*8 + ty;
        float v = s[tx][j*8 + ty];
        __nv_bfloat16 hi = __float2bfloat16(v);
        __nv_bfloat16 lo = __float2bfloat16(v - __bfloat162float(hi));
        size_t o = (size_t)(b*HW + px)*CPAD + ch0 + tx;
        g_atth[o] = hi;
        g_attl[o] = lo;
    }
}

// ---------------- kernel 5a: conv1 weights -> [t][c][co(144)][ci=64] bf16 hi/lo ----
__global__ void k_prepw(const float* __restrict__ w) {
    int i = blockIdx.x * 256 + threadIdx.x;
    if (i >= NTAP*NCHUNK*MIDC*64) return;
    int ci_in = i & 63;
    int co    = (i >> 6) % MIDC;
    int tc    = (i >> 6) / MIDC;
    int c     = tc % NCHUNK;
    int t     = tc / NCHUNK;
    int ci    = c*64 + ci_in;
    float v = (ci < IP) ? w[((size_t)co*IP + ci)*9 + t] : 0.f;
    __nv_bfloat16 hi = __float2bfloat16(v);
    __nv_bfloat16 lo = __float2bfloat16(v - __bfloat162float(hi));
    g_w1h[i] = hi;
    g_w1l[i] = lo;
}

// ---------------- kernel 5b: conv2 weights -> [t][c][co(56)][ci=64] bf16 hi/lo ----
__global__ void k_prepw2(const float* __restrict__ w) {
    int i = blockIdx.x * 256 + threadIdx.x;
    if (i >= NTAP*3*OPAD*64) return;
    int ci_in = i & 63;
    int co    = (i >> 6) % OPAD;
    int tc    = (i >> 6) / OPAD;
    int c     = tc % 3;
    int t     = tc / 3;
    int ci    = c*64 + ci_in;
    float v = (co < OPC && ci < MIDC) ? w[((size_t)co*MIDC + ci)*9 + t] : 0.f;
    __nv_bfloat16 hi = __float2bfloat16(v);
    __nv_bfloat16 lo = __float2bfloat16(v - __bfloat162float(hi));
    g_w2h[i] = hi;
    g_w2l[i] = lo;
}

// ---------------- kernel 6: conv1 implicit GEMM, epilogue writes NHWC bf16 hi/lo ------
#define STG_BYTES 69632       // A_hi 16K | A_lo 16K | B_hi 18K | B_lo 18K
#define OFF_AH 0
#define OFF_AL 16384
#define OFF_BH 32768
#define OFF_BL 51200
#define SM_BN   (2*STG_BYTES)
#define SMEM_G  (SM_BN + 3*MIDC*4 + 64)

__device__ __forceinline__ void stage_async(uint32_t sb_stage, int tid, int kc, int b, int y) {
    const int t = kc / NCHUNK, c = kc - t*NCHUNK;
    const int ky = t / 3, kx = t - ky*3;
    const int ysrc = y + ky - 1;
    const bool yok = ((unsigned)ysrc < (unsigned)HH);
    const int gyc = yok ? ysrc : 0;

#pragma unroll
    for (int j = 0; j < 8; j++) {
        int i = tid + j*256;
        int split = i >> 10, idx = i & 1023, px = idx >> 3, q = idx & 7;
        int xsrc = px + kx - 1;
        bool ok = yok && ((unsigned)xsrc < (unsigned)WW);
        int gxc = ok ? xsrc : 0;
        const __nv_bfloat16* src = split ? g_attl : g_atth;
        const void* gp = src + ((size_t)((b*HH + gyc)*WW + gxc))*CPAD + c*64 + q*8;
        uint32_t off = (uint32_t)(px*128 + q*16);
        cpa16(sb_stage + split*16384 + SWZ(off), gp, ok ? 16u : 0u);
    }
    const __nv_bfloat16* wh = g_w1h + (size_t)(t*NCHUNK + c)*MIDC*64;
    const __nv_bfloat16* wl = g_w1l + (size_t)(t*NCHUNK + c)*MIDC*64;
#pragma unroll
    for (int j = 0; j < 9; j++) {
        int i = tid + j*256;
        int split = (i >= 1152);
        int idx = i - split*1152, row = idx >> 3, q = idx & 7;
        const __nv_bfloat16* src = split ? wl : wh;
        uint32_t off = (uint32_t)(row*128 + q*16);
        cpa16(sb_stage + OFF_BH + split*18432 + SWZ(off), src + row*64 + q*8, 16u);
    }
}

__global__ __launch_bounds__(256, 1) void k_gemm1(const float* __restrict__ bg,
                                                  const float* __restrict__ bb,
                                                  const float* __restrict__ bm,
                                                  const float* __restrict__ bv) {
    extern __shared__ char smem[];
    const int tid  = threadIdx.x;
    const int wid  = tid >> 5, lane = tid & 31;
    const int y    = blockIdx.x & (HH - 1);
    const int b    = blockIdx.x >> 7;
    const uint32_t sb = smem_u32(smem);

    float* sScale = (float*)(smem + SM_BN);
    float* sMean  = sScale + MIDC;
    float* sBeta  = sMean + MIDC;
    if (tid < MIDC) {
        sScale[tid] = bg[tid] * rsqrtf(bv[tid] + 1e-5f);
        sMean[tid]  = bm[tid];
        sBeta[tid]  = bb[tid];
    }

    const int wm = wid & 3, wn = wid >> 2;

    const int gA = lane >> 3;
    const int arow_off = (lane & 7) + ((gA & 1) << 3);
    const uint32_t acol_g = (uint32_t)((gA >> 1) << 4);
    const uint32_t swzx   = (uint32_t)((lane & 7) << 4);
    const int brow_off = ((gA >> 1) << 3) + (lane & 7);
    const uint32_t bcol_g = (uint32_t)((gA & 1) << 4);
    const int l2 = lane & 15;
    const int b2row_off = 64 + (l2 & 7);
    const uint32_t b2col_g = (uint32_t)((l2 >> 3) << 4);
    const uint32_t swz2   = (uint32_t)((l2 & 7) << 4);

    float acc[2][9][4];
#pragma unroll
    for (int mf = 0; mf < 2; mf++)
#pragma unroll
        for (int nf = 0; nf < 9; nf++)
#pragma unroll
            for (int k = 0; k < 4; k++) acc[mf][nf][k] = 0.f;

    stage_async(sb, tid, 0, b, y);
    CPA_COMMIT();

    for (int kc = 0; kc < KCHUNKS; kc++) {
        if (kc + 1 < KCHUNKS) {
            stage_async(sb + ((kc + 1) & 1) * STG_BYTES, tid, kc + 1, b, y);
            CPA_COMMIT();
            CPA_WAIT1();
        } else {
            CPA_WAIT0();
        }
        __syncthreads();

        const uint32_t base = sb + (kc & 1) * STG_BYTES;
        const uint32_t aH = base + OFF_AH + (uint32_t)(wm * 32) * 128;
        const uint32_t aL = base + OFF_AL + (uint32_t)(wm * 32) * 128;
        const uint32_t bH = base + OFF_BH + (uint32_t)(wn * 72) * 128;
        const uint32_t bL = base + OFF_BL + (uint32_t)(wn * 72) * 128;

#pragma unroll
        for (int ks = 0; ks < 4; ks++) {
            uint32_t ah[2][4], al[2][4], bh[9][2], bl[9][2];
            const uint32_t colA = ((uint32_t)(ks * 32) + acol_g) ^ swzx;
#pragma unroll
            for (int mf = 0; mf < 2; mf++) {
                uint32_t ra = (uint32_t)(mf * 16 + arow_off) * 128;
                ldsm4(aH + ra + colA, ah[mf]);
                ldsm4(aL + ra + colA, al[mf]);
            }
            const uint32_t colB = ((uint32_t)(ks * 32) + bcol_g) ^ swzx;
#pragma unroll
            for (int nf = 0; nf < 8; nf += 2) {
                uint32_t rb = (uint32_t)(nf * 8 + brow_off) * 128;
                uint32_t tmp[4];
                ldsm4(bH + rb + colB, tmp);
                bh[nf][0] = tmp[0]; bh[nf][1] = tmp[1];
                bh[nf+1][0] = tmp[2]; bh[nf+1][1] = tmp[3];
                ldsm4(bL + rb + colB, tmp);
                bl[nf][0] = tmp[0]; bl[nf][1] = tmp[1];
                bl[nf+1][0] = tmp[2]; bl[nf+1][1] = tmp[3];
            }
            {
                const uint32_t colB2 = ((uint32_t)(ks * 32) + b2col_g) ^ swz2;
                uint32_t rb2 = (uint32_t)b2row_off * 128;
                ldsm2(bH + rb2 + colB2, bh[8]);
                ldsm2(bL + rb2 + colB2, bl[8]);
            }
#pragma unroll
            for (int nf = 0; nf < 9; nf++)
#pragma unroll
                for (int mf = 0; mf < 2; mf++) {
                    mma16816(acc[mf][nf], ah[mf], bh[nf]);
                    mma16816(acc[mf][nf], ah[mf], bl[nf]);
                    mma16816(acc[mf][nf], al[mf], bh[nf]);
                }
        }
        __syncthreads();
    }

    // epilogue: BN + GELU, split to bf16 hi/lo, write NHWC (CPAD2) for gemm2
#pragma unroll
    for (int mf = 0; mf < 2; mf++)
#pragma unroll
        for (int nf = 0; nf < 9; nf++) {
            int co0 = wn * 72 + nf * 8 + (lane & 3) * 2;
            int x0  = wm * 32 + mf * 16 + (lane >> 2);
#pragma unroll
            for (int hr = 0; hr < 2; hr++) {
                int x = x0 + hr * 8;
                float g0, g1;
                {
                    float v = acc[mf][nf][hr * 2 + 0];
                    g0 = gelu_exact((v - sMean[co0]) * sScale[co0] + sBeta[co0]);
                    v = acc[mf][nf][hr * 2 + 1];
                    g1 = gelu_exact((v - sMean[co0+1]) * sScale[co0+1] + sBeta[co0+1]);
                }
                __nv_bfloat16 h0 = __float2bfloat16(g0);
                __nv_bfloat16 h1 = __float2bfloat16(g1);
                __nv_bfloat16 l0 = __float2bfloat16(g0 - __bfloat162float(h0));
                __nv_bfloat16 l1 = __float2bfloat16(g1 - __bfloat162float(h1));
                size_t off = ((size_t)b*HW + y*WW + x) * CPAD2 + co0;
                __nv_bfloat162 ph; ph.x = h0; ph.y = h1;
                __nv_bfloat162 pl; pl.x = l0; pl.y = l1;
                *(__nv_bfloat162*)&g_midh[off] = ph;
                *(__nv_bfloat162*)&g_midl[off] = pl;
            }
        }
}

// ---------------- kernel 7: conv2 implicit GEMM on mma.sync ----------------
// M=128 px (one row), N=56 (49 pad), K = 9 taps * 3 chunks * 64 (144 pad 192).
#define STG2_BYTES 47104      // A_hi 16K | A_lo 16K | B_hi 7K | B_lo 7K
#define OFF2_AH 0
#define OFF2_AL 16384
#define OFF2_BH 32768
#define OFF2_BL 39936
#define SM2_BN  (2*STG2_BYTES)
#define SMEM_G2 (SM2_BN + 3*OPC*4 + 64)

__device__ __forceinline__ void stage_async2(uint32_t sb_stage, int tid, int kc, int b, int y) {
    const int t = kc / 3, c = kc - t*3;
    const int ky = t / 3, kx = t - ky*3;
    const int ysrc = y + ky - 1;
    const bool yok = ((unsigned)ysrc < (unsigned)HH);
    const int gyc = yok ? ysrc : 0;

#pragma unroll
    for (int j = 0; j < 8; j++) {
        int i = tid + j*256;
        int split = i >> 10, idx = i & 1023, px = idx >> 3, q = idx & 7;
        int xsrc = px + kx - 1;
        bool ok = yok && ((unsigned)xsrc < (unsigned)WW);
        int gxc = ok ? xsrc : 0;
        const __nv_bfloat16* src = split ? g_midl : g_midh;
        const void* gp = src + ((size_t)((b*HH + gyc)*WW + gxc))*CPAD2 + c*64 + q*8;
        uint32_t off = (uint32_t)(px*128 + q*16);
        cpa16(sb_stage + split*16384 + SWZ(off), gp, ok ? 16u : 0u);
    }
    const __nv_bfloat16* wh = g_w2h + (size_t)(t*3 + c)*OPAD*64;
    const __nv_bfloat16* wl = g_w2l + (size_t)(t*3 + c)*OPAD*64;
    for (int i = tid; i < 2*OPAD*8; i += 256) {
        int split = (i >= OPAD*8);
        int idx = i - split*OPAD*8, row = idx >> 3, q = idx & 7;
        const __nv_bfloat16* src = split ? wl : wh;
        uint32_t off = (uint32_t)(row*128 + q*16);
        cpa16(sb_stage + OFF2_BH + split*7168 + SWZ(off), src + row*64 + q*8, 16u);
    }
}

__global__ __launch_bounds__(256, 1) void k_gemm2(const float* __restrict__ bg,
                                                  const float* __restrict__ bb,
                                                  const float* __restrict__ bm,
                                                  const float* __restrict__ bv,
                                                  float* __restrict__ dout) {
    extern __shared__ char smem[];
    const int tid  = threadIdx.x;
    const int wid  = tid >> 5, lane = tid & 31;
    const int y    = blockIdx.x & (HH - 1);
    const int b    = blockIdx.x >> 7;
    const uint32_t sb = smem_u32(smem);

    float* sScale = (float*)(smem + SM2_BN);
    float* sMean  = sScale + OPC;
    float* sBeta  = sMean + OPC;
    if (tid < OPC) {
        sScale[tid] = bg[tid] * rsqrtf(bv[tid] + 1e-5f);
        sMean[tid]  = bm[tid];
        sBeta[tid]  = bb[tid];
    }

    const int gA = lane >> 3;
    const int arow_off = (lane & 7) + ((gA & 1) << 3);
    const uint32_t acol_g = (uint32_t)((gA >> 1) << 4);
    const uint32_t swzx   = (uint32_t)((lane & 7) << 4);
    const int brow_off = ((gA >> 1) << 3) + (lane & 7);
    const uint32_t bcol_g = (uint32_t)((gA & 1) << 4);
    const int l2 = lane & 15;
    const int b2row_off = 48 + (l2 & 7);
    const uint32_t b2col_g = (uint32_t)((l2 >> 3) << 4);
    const uint32_t swz2   = (uint32_t)((l2 & 7) << 4);

    float acc[7][4];
#pragma unroll
    for (int nf = 0; nf < 7; nf++)
#pragma unroll
        for (int k = 0; k < 4; k++) acc[nf][k] = 0.f;

    stage_async2(sb, tid, 0, b, y);
    CPA_COMMIT();

    for (int kc = 0; kc < KC2; kc++) {
        if (kc + 1 < KC2) {
            stage_async2(sb + ((kc + 1) & 1) * STG2_BYTES, tid, kc + 1, b, y);
            CPA_COMMIT();
            CPA_WAIT1();
        } else {
            CPA_WAIT0();
        }
        __syncthreads();

        const uint32_t base = sb + (kc & 1) * STG2_BYTES;
        const uint32_t aH = base + OFF2_AH + (uint32_t)(wid * 16) * 128;
        const uint32_t aL = base + OFF2_AL + (uint32_t)(wid * 16) * 128;
        const uint32_t bH = base + OFF2_BH;
        const uint32_t bL = base + OFF2_BL;

#pragma unroll
        for (int ks = 0; ks < 4; ks++) {
            uint32_t ah[4], al[4], bh[7][2], bl[7][2];
            const uint32_t colA = ((uint32_t)(ks * 32) + acol_g) ^ swzx;
            {
                uint32_t ra = (uint32_t)arow_off * 128;
                ldsm4(aH + ra + colA, ah);
                ldsm4(aL + ra + colA, al);
            }
            const uint32_t colB = ((uint32_t)(ks * 32) + bcol_g) ^ swzx;
#pragma unroll
            for (int nf = 0; nf < 6; nf += 2) {
                uint32_t rb = (uint32_t)(nf * 8 + brow_off) * 128;
                uint32_t tmp[4];
                ldsm4(bH + rb + colB, tmp);
                bh[nf][0] = tmp[0]; bh[nf][1] = tmp[1];
                bh[nf+1][0] = tmp[2]; bh[nf+1][1] = tmp[3];
                ldsm4(bL + rb + colB, tmp);
                bl[nf][0] = tmp[0]; bl[nf][1] = tmp[1];
                bl[nf+1][0] = tmp[2]; bl[nf+1][1] = tmp[3];
            }
            {
                const uint32_t colB2 = ((uint32_t)(ks * 32) + b2col_g) ^ swz2;
                uint32_t rb2 = (uint32_t)b2row_off * 128;
                ldsm2(bH + rb2 + colB2, bh[6]);
                ldsm2(bL + rb2 + colB2, bl[6]);
            }
#pragma unroll
            for (int nf = 0; nf < 7; nf++) {
                mma16816(acc[nf], ah, bh[nf]);
                mma16816(acc[nf], ah, bl[nf]);
                mma16816(acc[nf], al, bh[nf]);
            }
        }
        __syncthreads();
    }

    // epilogue: BN + GELU -> final fp32 NCHW output
#pragma unroll
    for (int nf = 0; nf < 7; nf++) {
        int co0 = nf * 8 + (lane & 3) * 2;
        int x0  = wid * 16 + (lane >> 2);
#pragma unroll
        for (int hr = 0; hr < 2; hr++) {
            int x = x0 + hr * 8;
#pragma unroll
            for (int dc = 0; dc < 2; dc++) {
                int co = co0 + dc;
                if (co < OPC) {
                    float v = acc[nf][hr * 2 + dc];
                    float gel = gelu_exact((v - sMean[co]) * sScale[co] + sBeta[co]);
                    dout[(((size_t)b*OPC + co)*HH + y)*WW + x] = gel;
                }
            }
        }
    }
}

// ---------------- launch ----------------
extern "C" void kernel_launch(void* const* d_in, const int* in_sizes, int n_in,
                              void* d_out, int out_size) {
    const float* f1    = (const float*)d_in[0];
    const float* f2    = (const float*)d_in[1];
    const float* att_w = (const float*)d_in[2];
    const float* att_b = (const float*)d_in[3];
    const float* c1_w  = (const float*)d_in[4];
    const float* bn1_g = (const float*)d_in[5];
    const float* bn1_b = (const float*)d_in[6];
    const float* bn1_m = (const float*)d_in[7];
    const float* bn1_v = (const float*)d_in[8];
    const float* c2_w  = (const float*)d_in[9];
    const float* bn2_g = (const float*)d_in[10];
    const float* bn2_b = (const float*)d_in[11];
    const float* bn2_m = (const float*)d_in[12];
    const float* bn2_v = (const float*)d_in[13];

    cudaFuncSetAttribute(k_gemm1, cudaFuncAttributeMaxDynamicSharedMemorySize, SMEM_G);
    cudaFuncSetAttribute(k_gemm2, cudaFuncAttributeMaxDynamicSharedMemorySize, SMEM_G2);

    k_rnorm<<<(BB_*HW + 255)/256, 256>>>(f1);
    k_costvol<<<dim3(WW/64, HH, BB_), 272>>>(f1, f2);
    k_att<<<dim3(WW/32, HH/8, BB_*IP), 256>>>(att_w, att_b);
    k_nhwc<<<dim3(HW/32, (IP+31)/32, BB_), 256>>>();
    k_prepw<<<(NTAP*NCHUNK*MIDC*64 + 255)/256, 256>>>(c1_w);
    k_prepw2<<<(NTAP*3*OPAD*64 + 255)/256, 256>>>(c2_w);
    k_gemm1<<<BB_*HH, 256, SMEM_G>>>(bn1_g, bn1_b, bn1_m, bn1_v);
    k_gemm2<<<BB_*HH, 256, SMEM_G2>>>(bn2_g, bn2_b, bn2_m, bn2_v, (float*)d_out);
}

// round 6
// speedup vs baseline: 2.7499x; 1.0184x over previous
#include <cuda_runtime.h>
#include <cuda_bf16.h>
#include <math.h>
#include <stdint.h>

#define BB_  2
#define CC   128
#define HH   128
#define WW   128
#define SRR  8
#define MOFF 17
#define IP   289
#define MIDC 144
#define OPC  49
#define HW   (HH*WW)

#define CPAD   320            // 289 padded to 5*64
#define NCHUNK 5
#define NTAP   9

#define CPAD2  192            // 144 padded to 3*64
#define OPAD   56             // 49 padded to 7*8

// ---------------- scratch (static device globals; no runtime allocation) ----------------
__device__ float g_rn [BB_*HW];
__device__ float g_mv [(size_t)BB_*IP*HW];
__device__ float g_att[(size_t)BB_*IP*HW];
__device__ __nv_bfloat16 g_atth[(size_t)BB_*HW*CPAD];   // NHWC hi split (conv1 input)
__device__ __nv_bfloat16 g_attl[(size_t)BB_*HW*CPAD];   // NHWC lo split
__device__ __nv_bfloat16 g_midh[(size_t)BB_*HW*CPAD2];  // NHWC hi split (conv2 input)
__device__ __nv_bfloat16 g_midl[(size_t)BB_*HW*CPAD2];  // NHWC lo split
__device__ __nv_bfloat16 g_w1h [NTAP*NCHUNK*MIDC*64];   // [t][c][co][ci]
__device__ __nv_bfloat16 g_w1l [NTAP*NCHUNK*MIDC*64];
__device__ __nv_bfloat16 g_w2h [NTAP*3*OPAD*64];        // [t][c][co][ci]
__device__ __nv_bfloat16 g_w2l [NTAP*3*OPAD*64];

// ---------------- helpers ----------------
__device__ __forceinline__ uint32_t smem_u32(const void* p) {
    uint32_t a;
    asm("{ .reg .u64 t; cvta.to.shared.u64 t, %1; cvt.u32.u64 %0, t; }" : "=r"(a) : "l"(p));
    return a;
}
#define SWZ(o) ((o) ^ (((o) >> 3) & 0x70))

__device__ __forceinline__ void cpa16(uint32_t saddr, const void* gaddr, uint32_t sz) {
    asm volatile("cp.async.cg.shared.global [%0], [%1], 16, %2;"
                 :: "r"(saddr), "l"(gaddr), "r"(sz));
}
#define CPA_COMMIT() asm volatile("cp.async.commit_group;" ::: "memory")
#define CPA_WAIT0()  asm volatile("cp.async.wait_group 0;" ::: "memory")
#define CPA_WAIT1()  asm volatile("cp.async.wait_group 1;" ::: "memory")

__device__ __forceinline__ void ldsm4(uint32_t addr, uint32_t* r) {
    asm volatile("ldmatrix.sync.aligned.m8n8.x4.shared.b16 {%0,%1,%2,%3}, [%4];"
                 : "=r"(r[0]), "=r"(r[1]), "=r"(r[2]), "=r"(r[3]) : "r"(addr));
}
__device__ __forceinline__ void ldsm2(uint32_t addr, uint32_t* r) {
    asm volatile("ldmatrix.sync.aligned.m8n8.x2.shared.b16 {%0,%1}, [%2];"
                 : "=r"(r[0]), "=r"(r[1]) : "r"(addr));
}
__device__ __forceinline__ void mma16816(float* d, const uint32_t* a, const uint32_t* b) {
    asm volatile("mma.sync.aligned.m16n8k16.row.col.f32.bf16.bf16.f32 "
                 "{%0,%1,%2,%3}, {%4,%5,%6,%7}, {%8,%9}, {%0,%1,%2,%3};"
                 : "+f"(d[0]), "+f"(d[1]), "+f"(d[2]), "+f"(d[3])
                 : "r"(a[0]), "r"(a[1]), "r"(a[2]), "r"(a[3]), "r"(b[0]), "r"(b[1]));
}
__device__ __forceinline__ float gelu_exact(float z) {
    return 0.5f * z * (1.f + erff(z * 0.70710678118654752440f));
}

// ---------------- kernel 1: per-pixel inverse L2 norm of f1 over channels ----------------
__global__ void k_rnorm(const float* __restrict__ f1) {
    int idx = blockIdx.x * 256 + threadIdx.x;
    if (idx >= BB_*HW) return;
    int b = idx / HW, p = idx % HW;
    const float* base = f1 + (size_t)b*CC*HW + p;
    float s = 0.f;
#pragma unroll 8
    for (int c = 0; c < CC; c++) { float v = base[(size_t)c*HW]; s = fmaf(v, v, s); }
    g_rn[idx] = 1.f / fmaxf(sqrtf(s), 1e-12f);
}

// ---------------- kernel 2: cost volume, cp.async triple-buffered ----------------
__global__ __launch_bounds__(272) void k_costvol(const float* __restrict__ f1,
                                                 const float* __restrict__ f2) {
    __shared__ float s_x1[3][64];
    __shared__ float s_f2[3][MOFF*80];

    const int x0  = blockIdx.x * 64;
    const int h   = blockIdx.y;
    const int b   = blockIdx.z;
    const int tid = threadIdx.x;
    const int g   = tid & 15;
    const int dy  = tid >> 4;

    const float* f1b = f1 + (size_t)b*CC*HW;
    const float* f2b = f2 + (size_t)b*CC*HW;

    int   goff[2];  uint32_t smoff[2];  uint32_t csz[2];  int nslot = 1;
    {
        int slots[2] = { tid, tid + 272 };
        if (slots[1] < 340) nslot = 2;
#pragma unroll
        for (int k = 0; k < 2; k++) {
            int sl = slots[k] < 340 ? slots[k] : 0;
            int r = sl / 20, col4 = (sl % 20) * 4;
            int gy = h + r - SRR, gx0 = x0 + col4 - SRR;
            bool ok = (gy >= 0 && gy < HH && gx0 >= 0 && gx0 <= WW - 4);
            goff[k]  = ok ? (gy*WW + gx0) : 0;
            csz[k]   = ok ? 16u : 0u;
            smoff[k] = (uint32_t)((r*80 + col4) * 4);
        }
    }
    const uint32_t sb_f2 = smem_u32(&s_f2[0][0]);

    float rnv = 0.f;  const float* x1p = nullptr;
    if (tid < 64) {
        rnv = g_rn[(size_t)b*HW + h*WW + x0 + tid];
        x1p = f1b + h*WW + x0 + tid;
    }

    float acc[MOFF][4];
#pragma unroll
    for (int d = 0; d < MOFF; d++)
#pragma unroll
        for (int j = 0; j < 4; j++) acc[d][j] = 0.f;

    {
        const float* src = f2b;
        cpa16(sb_f2 + smoff[0], src + goff[0], csz[0]);
        if (nslot == 2) cpa16(sb_f2 + smoff[1], src + goff[1], csz[1]);
        CPA_COMMIT();
    }
    float x1cur = (tid < 64) ? x1p[0] : 0.f;
    float x1nxt = 0.f;

    for (int c = 0; c < CC; c++) {
        const int buf = c - (c/3)*3;
        if (c + 1 < CC) {
            if (tid < 64) x1nxt = x1p[(size_t)(c+1)*HW];
            const int nbuf = (c+1) - ((c+1)/3)*3;
            const float* src = f2b + (size_t)(c+1)*HW;
            uint32_t base = sb_f2 + (uint32_t)nbuf * (MOFF*80*4);
            cpa16(base + smoff[0], src + goff[0], csz[0]);
            if (nslot == 2) cpa16(base + smoff[1], src + goff[1], csz[1]);
            CPA_COMMIT();
            CPA_WAIT1();
        } else {
            CPA_WAIT0();
        }
        if (tid < 64) s_x1[buf][tid] = x1cur * rnv;
        __syncthreads();

        float4 x1v = *(const float4*)&s_x1[buf][g*4];
        float f2v[20];
        const float* row = &s_f2[buf][dy*80 + g*4];
#pragma unroll
        for (int q = 0; q < 5; q++) {
            float4 t = *(const float4*)&row[q*4];
            f2v[q*4+0] = t.x; f2v[q*4+1] = t.y; f2v[q*4+2] = t.z; f2v[q*4+3] = t.w;
        }
#pragma unroll
        for (int dx = 0; dx < MOFF; dx++) {
            acc[dx][0] = fmaf(x1v.x, f2v[dx+0], acc[dx][0]);
            acc[dx][1] = fmaf(x1v.y, f2v[dx+1], acc[dx][1]);
            acc[dx][2] = fmaf(x1v.z, f2v[dx+2], acc[dx][2]);
            acc[dx][3] = fmaf(x1v.w, f2v[dx+3], acc[dx][3]);
        }
        x1cur = x1nxt;
        __syncthreads();
    }

#pragma unroll
    for (int dx = 0; dx < MOFF; dx++) {
        float4 o;
        float* op = (float*)&o;
#pragma unroll
        for (int j = 0; j < 4; j++) {
            float v = acc[dx][j] * 0.0078125f;
            op[j] = v > 0.f ? v : 0.1f * v;
        }
        int ch = dy*MOFF + dx;
        *(float4*)&g_mv[(((size_t)b*IP + ch)*HH + h)*WW + x0 + g*4] = o;
    }
}

// ---------------- kernel 3: depthwise 7x7 att conv + bias, att_vol = mv*att ----------
__global__ void k_att(const float* __restrict__ att_w, const float* __restrict__ att_b) {
    __shared__ float s_in[14*38];
    __shared__ float s_w[49];

    const int bz = blockIdx.z;
    const int b  = bz / IP;
    const int ch = bz % IP;
    const int x0 = blockIdx.x * 32;
    const int y0 = blockIdx.y * 8;
    const int tid = threadIdx.x;

    const float* mvp = g_mv + ((size_t)b*IP + ch)*HW;
    for (int i = tid; i < 14*38; i += 256) {
        int r = i / 38, cl = i % 38;
        int gy = y0 + r - 3, gx = x0 + cl - 3;
        s_in[i] = (gy >= 0 && gy < HH && gx >= 0 && gx < WW) ? mvp[gy*WW + gx] : 0.f;
    }
    if (tid < 49) s_w[tid] = att_w[ch*49 + tid];
    __syncthreads();

    const int tx = tid & 31, ty = tid >> 5;
    float s = att_b[ch];
#pragma unroll
    for (int ky = 0; ky < 7; ky++)
#pragma unroll
        for (int kx = 0; kx < 7; kx++)
            s = fmaf(s_w[ky*7+kx], s_in[(ty+ky)*38 + tx + kx], s);

    float center = s_in[(ty+3)*38 + tx + 3];
    g_att[((size_t)b*IP + ch)*HW + (y0+ty)*WW + x0 + tx] = center * s;
}

// ---------------- kernel 4: transpose NCHW fp32 -> NHWC bf16 hi/lo (C padded 320) ----
__global__ __launch_bounds__(256) void k_nhwc() {
    __shared__ float s[32][33];
    const int tid = threadIdx.x;
    const int tx = tid & 31, ty = tid >> 5;
    const int px0 = blockIdx.x * 32;
    const int ch0 = blockIdx.y * 32;
    const int b   = blockIdx.z;

#pragma unroll
    for (int j = 0; j < 4; j++) {
        int ch = ch0 + j*8 + ty;
        s[j*8 + ty][tx] = (ch < IP) ? g_att[((size_t)b*IP + ch)*HW + px0 + tx] : 0.f;
    }
    __syncthreads();
#pragma unroll
    for (int j = 0; j < 4; j++) {
        int px = px0 + j*8 + ty;
        float v = s[tx][j*8 + ty];
        __nv_bfloat16 hi = __float2bfloat16(v);
        __nv_bfloat16 lo = __float2bfloat16(v - __bfloat162float(hi));
        size_t o = (size_t)(b*HW + px)*CPAD + ch0 + tx;
        g_atth[o] = hi;
        g_attl[o] = lo;
    }
}

// ---------------- kernel 5a/5b: weight prep ----------------
__global__ void k_prepw(const float* __restrict__ w) {
    int i = blockIdx.x * 256 + threadIdx.x;
    if (i >= NTAP*NCHUNK*MIDC*64) return;
    int ci_in = i & 63;
    int co    = (i >> 6) % MIDC;
    int tc    = (i >> 6) / MIDC;
    int c     = tc % NCHUNK;
    int t     = tc / NCHUNK;
    int ci    = c*64 + ci_in;
    float v = (ci < IP) ? w[((size_t)co*IP + ci)*9 + t] : 0.f;
    __nv_bfloat16 hi = __float2bfloat16(v);
    __nv_bfloat16 lo = __float2bfloat16(v - __bfloat162float(hi));
    g_w1h[i] = hi;
    g_w1l[i] = lo;
}
__global__ void k_prepw2(const float* __restrict__ w) {
    int i = blockIdx.x * 256 + threadIdx.x;
    if (i >= NTAP*3*OPAD*64) return;
    int ci_in = i & 63;
    int co    = (i >> 6) % OPAD;
    int tc    = (i >> 6) / OPAD;
    int c     = tc % 3;
    int t     = tc / 3;
    int ci    = c*64 + ci_in;
    float v = (co < OPC && ci < MIDC) ? w[((size_t)co*MIDC + ci)*9 + t] : 0.f;
    __nv_bfloat16 hi = __float2bfloat16(v);
    __nv_bfloat16 lo = __float2bfloat16(v - __bfloat162float(hi));
    g_w2h[i] = hi;
    g_w2l[i] = lo;
}

// ================= kernel 6: conv1 implicit GEMM, M=256 (2 rows), A-chunk-resident =====
// A resident: 2 splits x (4 src rows x 132 px) x 64 ch, reused across all 9 taps.
// B double-buffered per (tap, chunk).
#define G1_ASPL 67584                 // 528 rows * 128B
#define G1_BOFF (2*G1_ASPL)           // 135168
#define G1_BSTG 36864
#define G1_BSPL 18432
#define G1_BN   (G1_BOFF + 2*G1_BSTG) // 208896
#define G1_SMEM (G1_BN + 3*MIDC*4 + 64)

__device__ __forceinline__ void g1_stageA(uint32_t sbA, int tid, int c, int b, int y0) {
#pragma unroll 3
    for (int j = 0; j < 33; j++) {
        int i = tid + j*256;
        int split = (i >= 4224);
        int idx = i - split*4224;
        int row = idx >> 3, q = idx & 7;
        int yrel = row / 132;
        int pxh  = row - yrel*132;
        int ysrc = y0 - 1 + yrel, xsrc = pxh - 1;
        bool ok = ((unsigned)ysrc < (unsigned)HH) && ((unsigned)xsrc < (unsigned)WW);
        const __nv_bfloat16* src = split ? g_attl : g_atth;
        const void* gp = src + ((size_t)((b*HH + (ok?ysrc:0))*WW + (ok?xsrc:0)))*CPAD + c*64 + q*8;
        cpa16(sbA + (uint32_t)split*G1_ASPL + SWZ((uint32_t)(row*128 + q*16)), gp, ok ? 16u : 0u);
    }
}
__device__ __forceinline__ void g1_stageB(uint32_t sbB, int tid, int t, int c) {
    const __nv_bfloat16* wh = g_w1h + (size_t)(t*NCHUNK + c)*MIDC*64;
    const __nv_bfloat16* wl = g_w1l + (size_t)(t*NCHUNK + c)*MIDC*64;
#pragma unroll
    for (int j = 0; j < 9; j++) {
        int i = tid + j*256;
        int split = (i >= 1152);
        int idx = i - split*1152, row = idx >> 3, q = idx & 7;
        const __nv_bfloat16* src = split ? wl : wh;
        cpa16(sbB + (uint32_t)split*G1_BSPL + SWZ((uint32_t)(row*128 + q*16)), src + row*64 + q*8, 16u);
    }
}

__global__ __launch_bounds__(256, 1) void k_gemm1(const float* __restrict__ bg,
                                                  const float* __restrict__ bb,
                                                  const float* __restrict__ bm,
                                                  const float* __restrict__ bv) {
    extern __shared__ char smem[];
    const int tid  = threadIdx.x;
    const int wid  = tid >> 5, lane = tid & 31;
    const int y0   = (blockIdx.x & 63) * 2;
    const int b    = blockIdx.x >> 6;
    const uint32_t sb = smem_u32(smem);

    float* sScale = (float*)(smem + G1_BN);
    float* sMean  = sScale + MIDC;
    float* sBeta  = sMean + MIDC;
    if (tid < MIDC) {
        sScale[tid] = bg[tid] * rsqrtf(bv[tid] + 1e-5f);
        sMean[tid]  = bm[tid];
        sBeta[tid]  = bb[tid];
    }

    const int wm = wid >> 1, wn = wid & 1;
    const int ywarp = wm >> 1;            // 0/1 -> output row y0 + ywarp
    const int pxb   = (wm & 1) * 64;      // px base

    const int gA = lane >> 3;
    const int arow_off = (lane & 7) + ((gA & 1) << 3);
    const uint32_t acol_g = (uint32_t)((gA >> 1) << 4);
    const uint32_t swzx   = (uint32_t)((lane & 7) << 4);
    const int brow_off = ((gA >> 1) << 3) + (lane & 7);
    const uint32_t bcol_g = (uint32_t)((gA & 1) << 4);
    const int l2 = lane & 15;
    const int b2row_off = 64 + (l2 & 7);
    const uint32_t b2col_g = (uint32_t)((l2 >> 3) << 4);
    const uint32_t swz2   = (uint32_t)((l2 & 7) << 4);

    float acc[4][9][4];
#pragma unroll
    for (int mf = 0; mf < 4; mf++)
#pragma unroll
        for (int nf = 0; nf < 9; nf++)
#pragma unroll
            for (int k = 0; k < 4; k++) acc[mf][nf][k] = 0.f;

    g1_stageA(sb, tid, 0, b, y0);
    g1_stageB(sb + G1_BOFF, tid, 0, 0);
    CPA_COMMIT();

    int s = 0;
    for (int c = 0; c < NCHUNK; c++) {
        if (c > 0) { g1_stageA(sb, tid, c, b, y0); CPA_COMMIT(); }
        for (int t = 0; t < NTAP; t++, s++) {
            if (s + 1 < NTAP*NCHUNK) {
                int t1 = (t + 1 < NTAP) ? t + 1 : 0;
                int c1 = (t + 1 < NTAP) ? c : c + 1;
                g1_stageB(sb + G1_BOFF + (uint32_t)((s + 1) & 1)*G1_BSTG, tid, t1, c1);
                CPA_COMMIT();
                CPA_WAIT1();
            } else {
                CPA_WAIT0();
            }
            __syncthreads();

            const int ky = t / 3, kx = t - ky*3;
            const uint32_t bBase = sb + G1_BOFF + (uint32_t)(s & 1)*G1_BSTG + (uint32_t)(wn*72)*128;
            const int arbase = (ky + ywarp)*132 + pxb + kx;

#pragma unroll
            for (int ks = 0; ks < 4; ks++) {
                uint32_t bh[9][2], bl[9][2];
                const uint32_t colB = ((uint32_t)(ks * 32) + bcol_g) ^ swzx;
#pragma unroll
                for (int nf = 0; nf < 8; nf += 2) {
                    uint32_t rb = (uint32_t)(nf * 8 + brow_off) * 128;
                    uint32_t tmp[4];
                    ldsm4(bBase + rb + colB, tmp);
                    bh[nf][0] = tmp[0]; bh[nf][1] = tmp[1];
                    bh[nf+1][0] = tmp[2]; bh[nf+1][1] = tmp[3];
                    ldsm4(bBase + G1_BSPL + rb + colB, tmp);
                    bl[nf][0] = tmp[0]; bl[nf][1] = tmp[1];
                    bl[nf+1][0] = tmp[2]; bl[nf+1][1] = tmp[3];
                }
                {
                    const uint32_t colB2 = ((uint32_t)(ks * 32) + b2col_g) ^ swz2;
                    uint32_t rb2 = (uint32_t)b2row_off * 128;
                    ldsm2(bBase + rb2 + colB2, bh[8]);
                    ldsm2(bBase + G1_BSPL + rb2 + colB2, bl[8]);
                }
                const uint32_t colA_base = (uint32_t)(ks * 32) + acol_g;
#pragma unroll
                for (int mf = 0; mf < 4; mf++) {
                    int arow = arbase + mf*16 + arow_off;
                    uint32_t aaddr = sb + (uint32_t)arow*128
                                   + (colA_base ^ (((uint32_t)arow & 7) << 4));
                    uint32_t ah[4], al[4];
                    ldsm4(aaddr, ah);
                    ldsm4(aaddr + G1_ASPL, al);
#pragma unroll
                    for (int nf = 0; nf < 9; nf++) {
                        mma16816(acc[mf][nf], ah, bh[nf]);
                        mma16816(acc[mf][nf], ah, bl[nf]);
                        mma16816(acc[mf][nf], al, bh[nf]);
                    }
                }
            }
            __syncthreads();
        }
    }

    // epilogue: BN + GELU, split to bf16 hi/lo, write NHWC (CPAD2) for gemm2
    const int yout = y0 + ywarp;
#pragma unroll
    for (int mf = 0; mf < 4; mf++)
#pragma unroll
        for (int nf = 0; nf < 9; nf++) {
            int co0 = wn * 72 + nf * 8 + (lane & 3) * 2;
            int x0  = pxb + mf * 16 + (lane >> 2);
#pragma unroll
            for (int hr = 0; hr < 2; hr++) {
                int x = x0 + hr * 8;
                float v0 = acc[mf][nf][hr * 2 + 0];
                float v1 = acc[mf][nf][hr * 2 + 1];
                float g0 = gelu_exact((v0 - sMean[co0]) * sScale[co0] + sBeta[co0]);
                float g1 = gelu_exact((v1 - sMean[co0+1]) * sScale[co0+1] + sBeta[co0+1]);
                __nv_bfloat16 h0 = __float2bfloat16(g0);
                __nv_bfloat16 h1 = __float2bfloat16(g1);
                __nv_bfloat16 l0 = __float2bfloat16(g0 - __bfloat162float(h0));
                __nv_bfloat16 l1 = __float2bfloat16(g1 - __bfloat162float(h1));
                size_t off = ((size_t)b*HW + yout*WW + x) * CPAD2 + co0;
                __nv_bfloat162 ph; ph.x = h0; ph.y = h1;
                __nv_bfloat162 pl; pl.x = l0; pl.y = l1;
                *(__nv_bfloat162*)&g_midh[off] = ph;
                *(__nv_bfloat162*)&g_midl[off] = pl;
            }
        }
}

// ================= kernel 7: conv2 implicit GEMM, M=256, A-chunk-resident =============
#define G2_ASPL 67584
#define G2_BOFF (2*G2_ASPL)
#define G2_BSTG 14336
#define G2_BSPL 7168
#define G2_BN   (G2_BOFF + 2*G2_BSTG)   // 163840
#define G2_SMEM (G2_BN + 3*OPC*4 + 64)

__device__ __forceinline__ void g2_stageA(uint32_t sbA, int tid, int c, int b, int y0) {
#pragma unroll 3
    for (int j = 0; j < 33; j++) {
        int i = tid + j*256;
        int split = (i >= 4224);
        int idx = i - split*4224;
        int row = idx >> 3, q = idx & 7;
        int yrel = row / 132;
        int pxh  = row - yrel*132;
        int ysrc = y0 - 1 + yrel, xsrc = pxh - 1;
        bool ok = ((unsigned)ysrc < (unsigned)HH) && ((unsigned)xsrc < (unsigned)WW);
        const __nv_bfloat16* src = split ? g_midl : g_midh;
        const void* gp = src + ((size_t)((b*HH + (ok?ysrc:0))*WW + (ok?xsrc:0)))*CPAD2 + c*64 + q*8;
        cpa16(sbA + (uint32_t)split*G2_ASPL + SWZ((uint32_t)(row*128 + q*16)), gp, ok ? 16u : 0u);
    }
}
__device__ __forceinline__ void g2_stageB(uint32_t sbB, int tid, int t, int c) {
    const __nv_bfloat16* wh = g_w2h + (size_t)(t*3 + c)*OPAD*64;
    const __nv_bfloat16* wl = g_w2l + (size_t)(t*3 + c)*OPAD*64;
    for (int i = tid; i < 2*OPAD*8; i += 256) {
        int split = (i >= OPAD*8);
        int idx = i - split*OPAD*8, row = idx >> 3, q = idx & 7;
        const __nv_bfloat16* src = split ? wl : wh;
        cpa16(sbB + (uint32_t)split*G2_BSPL + SWZ((uint32_t)(row*128 + q*16)), src + row*64 + q*8, 16u);
    }
}

__global__ __launch_bounds__(256, 1) void k_gemm2(const float* __restrict__ bg,
                                                  const float* __restrict__ bb,
                                                  const float* __restrict__ bm,
                                                  const float* __restrict__ bv,
                                                  float* __restrict__ dout) {
    extern __shared__ char smem[];
    const int tid  = threadIdx.x;
    const int wid  = tid >> 5, lane = tid & 31;
    const int y0   = (blockIdx.x & 63) * 2;
    const int b    = blockIdx.x >> 6;
    const uint32_t sb = smem_u32(smem);

    float* sScale = (float*)(smem + G2_BN);
    float* sMean  = sScale + OPC;
    float* sBeta  = sMean + OPC;
    if (tid < OPC) {
        sScale[tid] = bg[tid] * rsqrtf(bv[tid] + 1e-5f);
        sMean[tid]  = bm[tid];
        sBeta[tid]  = bb[tid];
    }

    const int ywarp = wid >> 2;          // 0/1
    const int pxb   = (wid & 3) * 32;

    const int gA = lane >> 3;
    const int arow_off = (lane & 7) + ((gA & 1) << 3);
    const uint32_t acol_g = (uint32_t)((gA >> 1) << 4);
    const uint32_t swzx   = (uint32_t)((lane & 7) << 4);
    const int brow_off = ((gA >> 1) << 3) + (lane & 7);
    const uint32_t bcol_g = (uint32_t)((gA & 1) << 4);
    const int l2 = lane & 15;
    const int b2row_off = 48 + (l2 & 7);
    const uint32_t b2col_g = (uint32_t)((l2 >> 3) << 4);
    const uint32_t swz2   = (uint32_t)((l2 & 7) << 4);

    float acc[2][7][4];
#pragma unroll
    for (int mf = 0; mf < 2; mf++)
#pragma unroll
        for (int nf = 0; nf < 7; nf++)
#pragma unroll
            for (int k = 0; k < 4; k++) acc[mf][nf][k] = 0.f;

    g2_stageA(sb, tid, 0, b, y0);
    g2_stageB(sb + G2_BOFF, tid, 0, 0);
    CPA_COMMIT();

    int s = 0;
    for (int c = 0; c < 3; c++) {
        if (c > 0) { g2_stageA(sb, tid, c, b, y0); CPA_COMMIT(); }
        for (int t = 0; t < NTAP; t++, s++) {
            if (s + 1 < NTAP*3) {
                int t1 = (t + 1 < NTAP) ? t + 1 : 0;
                int c1 = (t + 1 < NTAP) ? c : c + 1;
                g2_stageB(sb + G2_BOFF + (uint32_t)((s + 1) & 1)*G2_BSTG, tid, t1, c1);
                CPA_COMMIT();
                CPA_WAIT1();
            } else {
                CPA_WAIT0();
            }
            __syncthreads();

            const int ky = t / 3, kx = t - ky*3;
            const uint32_t bBase = sb + G2_BOFF + (uint32_t)(s & 1)*G2_BSTG;
            const int arbase = (ky + ywarp)*132 + pxb + kx;

#pragma unroll
            for (int ks = 0; ks < 4; ks++) {
                uint32_t bh[7][2], bl[7][2];
                const uint32_t colB = ((uint32_t)(ks * 32) + bcol_g) ^ swzx;
#pragma unroll
                for (int nf = 0; nf < 6; nf += 2) {
                    uint32_t rb = (uint32_t)(nf * 8 + brow_off) * 128;
                    uint32_t tmp[4];
                    ldsm4(bBase + rb + colB, tmp);
                    bh[nf][0] = tmp[0]; bh[nf][1] = tmp[1];
                    bh[nf+1][0] = tmp[2]; bh[nf+1][1] = tmp[3];
                    ldsm4(bBase + G2_BSPL + rb + colB, tmp);
                    bl[nf][0] = tmp[0]; bl[nf][1] = tmp[1];
                    bl[nf+1][0] = tmp[2]; bl[nf+1][1] = tmp[3];
                }
                {
                    const uint32_t colB2 = ((uint32_t)(ks * 32) + b2col_g) ^ swz2;
                    uint32_t rb2 = (uint32_t)b2row_off * 128;
                    ldsm2(bBase + rb2 + colB2, bh[6]);
                    ldsm2(bBase + G2_BSPL + rb2 + colB2, bl[6]);
                }
                const uint32_t colA_base = (uint32_t)(ks * 32) + acol_g;
#pragma unroll
                for (int mf = 0; mf < 2; mf++) {
                    int arow = arbase + mf*16 + arow_off;
                    uint32_t aaddr = sb + (uint32_t)arow*128
                                   + (colA_base ^ (((uint32_t)arow & 7) << 4));
                    uint32_t ah[4], al[4];
                    ldsm4(aaddr, ah);
                    ldsm4(aaddr + G2_ASPL, al);
#pragma unroll
                    for (int nf = 0; nf < 7; nf++) {
                        mma16816(acc[mf][nf], ah, bh[nf]);
                        mma16816(acc[mf][nf], ah, bl[nf]);
                        mma16816(acc[mf][nf], al, bh[nf]);
                    }
                }
            }
            __syncthreads();
        }
    }

    const int yout = y0 + ywarp;
#pragma unroll
    for (int mf = 0; mf < 2; mf++)
#pragma unroll
        for (int nf = 0; nf < 7; nf++) {
            int co0 = nf * 8 + (lane & 3) * 2;
            int x0  = pxb + mf * 16 + (lane >> 2);
#pragma unroll
            for (int hr = 0; hr < 2; hr++) {
                int x = x0 + hr * 8;
#pragma unroll
                for (int dc = 0; dc < 2; dc++) {
                    int co = co0 + dc;
                    if (co < OPC) {
                        float v = acc[mf][nf][hr * 2 + dc];
                        float gel = gelu_exact((v - sMean[co]) * sScale[co] + sBeta[co]);
                        dout[(((size_t)b*OPC + co)*HH + yout)*WW + x] = gel;
                    }
                }
            }
        }
}

// ---------------- launch ----------------
extern "C" void kernel_launch(void* const* d_in, const int* in_sizes, int n_in,
                              void* d_out, int out_size) {
    const float* f1    = (const float*)d_in[0];
    const float* f2    = (const float*)d_in[1];
    const float* att_w = (const float*)d_in[2];
    const float* att_b = (const float*)d_in[3];
    const float* c1_w  = (const float*)d_in[4];
    const float* bn1_g = (const float*)d_in[5];
    const float* bn1_b = (const float*)d_in[6];
    const float* bn1_m = (const float*)d_in[7];
    const float* bn1_v = (const float*)d_in[8];
    const float* c2_w  = (const float*)d_in[9];
    const float* bn2_g = (const float*)d_in[10];
    const float* bn2_b = (const float*)d_in[11];
    const float* bn2_m = (const float*)d_in[12];
    const float* bn2_v = (const float*)d_in[13];

    cudaFuncSetAttribute(k_gemm1, cudaFuncAttributeMaxDynamicSharedMemorySize, G1_SMEM);
    cudaFuncSetAttribute(k_gemm2, cudaFuncAttributeMaxDynamicSharedMemorySize, G2_SMEM);

    k_rnorm<<<(BB_*HW + 255)/256, 256>>>(f1);
    k_costvol<<<dim3(WW/64, HH, BB_), 272>>>(f1, f2);
    k_att<<<dim3(WW/32, HH/8, BB_*IP), 256>>>(att_w, att_b);
    k_nhwc<<<dim3(HW/32, (IP+31)/32, BB_), 256>>>();
    k_prepw<<<(NTAP*NCHUNK*MIDC*64 + 255)/256, 256>>>(c1_w);
    k_prepw2<<<(NTAP*3*OPAD*64 + 255)/256, 256>>>(c2_w);
    k_gemm1<<<BB_*64, 256, G1_SMEM>>>(bn1_g, bn1_b, bn1_m, bn1_v);
    k_gemm2<<<BB_*64, 256, G2_SMEM>>>(bn2_g, bn2_b, bn2_m, bn2_v, (float*)d_out);
}